// round 4
// baseline (speedup 1.0000x reference)
#include <cuda_runtime.h>

// Problem constants
#define HEADS 4
#define HD 32
#define NTOK 98
#define CDIM 128
#define KDIM 128

static __device__ __constant__ float SCALE_C = 0.17677669529663687f; // 32^-0.5

// Scratch (device globals; no allocation allowed)
__device__ float g_q[(size_t)2048 * HEADS * NTOK * HD];
__device__ float g_k[(size_t)2048 * HEADS * NTOK * HD];
__device__ float g_v[(size_t)2048 * HEADS * NTOK * HD];
__device__ float g_o[(size_t)2048 * NTOK * CDIM];

// C[M, Nout] = A[M,128] @ W[Nout,128]^T + bias
// epi==0: scatter into g_q/g_k/g_v (q scaled).  epi==1: A := g_o, write Cout.
__global__ __launch_bounds__(256) void gemm64(const float* __restrict__ A,
                                              const float* __restrict__ W,
                                              const float* __restrict__ bias,
                                              float* __restrict__ Cout,
                                              int epi)
{
    __shared__ float As[16][64];
    __shared__ float Bs[16][64];

    const float* Ap = (epi == 1) ? (const float*)g_o : A;

    int tid = threadIdx.x;
    int tx = tid & 15;        // n-dir
    int ty = tid >> 4;        // m-dir
    int m0 = blockIdx.x * 64;
    int n0 = blockIdx.y * 64;
    int lr = tid >> 2;        // 0..63 (row within tile)
    int lc = (tid & 3) * 4;   // 0,4,8,12 (k offset)

    float acc[4][4] = {};

    for (int k0 = 0; k0 < KDIM; k0 += 16) {
        float4 av = *(const float4*)(Ap + (size_t)(m0 + lr) * KDIM + k0 + lc);
        As[lc + 0][lr] = av.x; As[lc + 1][lr] = av.y;
        As[lc + 2][lr] = av.z; As[lc + 3][lr] = av.w;
        float4 bv = *(const float4*)(W + (size_t)(n0 + lr) * KDIM + k0 + lc);
        Bs[lc + 0][lr] = bv.x; Bs[lc + 1][lr] = bv.y;
        Bs[lc + 2][lr] = bv.z; Bs[lc + 3][lr] = bv.w;
        __syncthreads();
        #pragma unroll
        for (int kk = 0; kk < 16; kk++) {
            float4 a = *(const float4*)&As[kk][ty * 4];
            float4 b = *(const float4*)&Bs[kk][tx * 4];
            float ar[4] = {a.x, a.y, a.z, a.w};
            float br[4] = {b.x, b.y, b.z, b.w};
            #pragma unroll
            for (int i = 0; i < 4; i++)
                #pragma unroll
                for (int j = 0; j < 4; j++)
                    acc[i][j] += ar[i] * br[j];
        }
        __syncthreads();
    }

    #pragma unroll
    for (int i = 0; i < 4; i++) {
        int m = m0 + ty * 4 + i;
        int b = m / NTOK;
        int nn = m - b * NTOK;
        #pragma unroll
        for (int j = 0; j < 4; j++) {
            int n = n0 + tx * 4 + j;
            float val = acc[i][j] + bias[n];
            if (epi == 0) {
                int which = n >> 7;        // 0=q,1=k,2=v
                int cc = n & 127;
                int h = cc >> 5;
                int d = cc & 31;
                size_t dst = ((size_t)(b * HEADS + h) * NTOK + nn) * HD + d;
                if (which == 0)      g_q[dst] = val * SCALE_C;
                else if (which == 1) g_k[dst] = val;
                else                 g_v[dst] = val;
            } else {
                Cout[(size_t)m * CDIM + n] = val;
            }
        }
    }
}

// One block per (window b, head h). Full attention in shared memory.
__global__ __launch_bounds__(256) void attn_kernel(const float* __restrict__ rel,
                                                   const float* __restrict__ mask,
                                                   int L)
{
    extern __shared__ float sm[];
    float* qs = sm;                 // 98*33
    float* ks = qs + NTOK * 33;     // 98*33
    float* vs = ks + NTOK * 33;     // 98*33
    float* Ss = vs + NTOK * 33;     // 98*99
    float* bs = Ss + NTOK * 99;     // 507
    float* rsum = bs + 507;         // 98

    int tid = threadIdx.x;
    int bh = blockIdx.x;
    int b = bh >> 2;
    int h = bh & 3;

    size_t base = (size_t)bh * (NTOK * HD);
    for (int idx = tid; idx < NTOK * HD; idx += 256) {
        int r = idx >> 5, c = idx & 31;
        qs[r * 33 + c] = g_q[base + idx];
        ks[r * 33 + c] = g_k[base + idx];
        vs[r * 33 + c] = g_v[base + idx];
    }
    for (int idx = tid; idx < 507; idx += 256) bs[idx] = rel[h * 507 + idx];
    __syncthreads();

    const float* mrow = mask + (size_t)(b % L) * (NTOK * NTOK);

    // S = q @ k^T + bias + mask
    for (int idx = tid; idx < NTOK * NTOK; idx += 256) {
        int i = idx / NTOK;
        int j = idx - i * NTOK;
        float s = 0.f;
        #pragma unroll
        for (int d = 0; d < HD; d++) s += qs[i * 33 + d] * ks[j * 33 + d];
        int ti = i / 49, ri = i - ti * 49, hi = ri / 7, wi = ri - hi * 7;
        int tj = j / 49, rj = j - tj * 49, hj = rj / 7, wj = rj - hj * 7;
        int ridx = (ti - tj + 1) * 169 + (hi - hj + 6) * 13 + (wi - wj + 6);
        s += bs[ridx] + mrow[idx];
        Ss[i * 99 + j] = s;
    }
    __syncthreads();

    // Row softmax (one thread per row)
    if (tid < NTOK) {
        float mx = -1e30f;
        for (int j = 0; j < NTOK; j++) mx = fmaxf(mx, Ss[tid * 99 + j]);
        float sum = 0.f;
        for (int j = 0; j < NTOK; j++) {
            float e = __expf(Ss[tid * 99 + j] - mx);
            Ss[tid * 99 + j] = e;
            sum += e;
        }
        rsum[tid] = 1.f / sum;
    }
    __syncthreads();

    // O = P @ v  -> g_o in [B, N, C] layout
    for (int idx = tid; idx < NTOK * HD; idx += 256) {
        int i = idx >> 5, d = idx & 31;
        float acc = 0.f;
        #pragma unroll 2
        for (int j = 0; j < NTOK; j++) acc += Ss[i * 99 + j] * vs[j * 33 + d];
        g_o[((size_t)b * NTOK + i) * CDIM + h * HD + d] = acc * rsum[i];
    }
}

extern "C" void kernel_launch(void* const* d_in, const int* in_sizes, int n_in,
                              void* d_out, int out_size)
{
    const float* x      = (const float*)d_in[0];
    const float* mask   = (const float*)d_in[1];
    const float* qkv_w  = (const float*)d_in[2];
    const float* qkv_b  = (const float*)d_in[3];
    const float* rel    = (const float*)d_in[4];
    const float* proj_w = (const float*)d_in[5];
    const float* proj_b = (const float*)d_in[6];
    float* out = (float*)d_out;

    int B = in_sizes[0] / (NTOK * CDIM);        // 2048
    int L = in_sizes[1] / (NTOK * NTOK);        // 512
    int M = B * NTOK;                            // 200704

    const int smem_bytes = (NTOK * 33 * 3 + NTOK * 99 + 507 + NTOK) * (int)sizeof(float);
    cudaFuncSetAttribute(attn_kernel, cudaFuncAttributeMaxDynamicSharedMemorySize, smem_bytes);

    dim3 g1(M / 64, (3 * CDIM) / 64);           // (3136, 6)
    gemm64<<<g1, 256>>>(x, qkv_w, qkv_b, nullptr, 0);

    attn_kernel<<<B * HEADS, 256, smem_bytes>>>(rel, mask, L);

    dim3 g2(M / 64, CDIM / 64);                 // (3136, 2)
    gemm64<<<g2, 256>>>(nullptr, proj_w, proj_b, out, 1);
}

// round 5
// speedup vs baseline: 1.7325x; 1.7325x over previous
#include <cuda_runtime.h>

#define HEADS 4
#define HD 32
#define NTOK 98
#define CDIM 128

static __device__ __constant__ float SCALE_C = 0.17677669529663687f; // 32^-0.5

// Scratch (device globals; no allocation allowed)
__device__ float g_q[(size_t)2048 * HEADS * NTOK * HD];
__device__ float g_k[(size_t)2048 * HEADS * NTOK * HD];
__device__ float g_v[(size_t)2048 * HEADS * NTOK * HD];
__device__ float g_o[(size_t)2048 * NTOK * CDIM];

// C[M,Nout] = A[M,128] @ W[Nout,128]^T + bias.  128x128 block tile, 8x8 micro.
// epi==0: scatter into g_q/g_k/g_v (q scaled). epi==1: A := g_o, write Cout.
__global__ __launch_bounds__(256, 2) void gemm128(const float* __restrict__ A,
                                                  const float* __restrict__ W,
                                                  const float* __restrict__ bias,
                                                  float* __restrict__ Cout,
                                                  int epi)
{
    __shared__ float As[16][128];
    __shared__ float Bs[16][128];

    const float* Ap = (epi == 1) ? (const float*)g_o : A;

    int tid = threadIdx.x;
    int tx = tid & 15;        // n-dir
    int ty = tid >> 4;        // m-dir
    int m0 = blockIdx.x * 128;
    int n0 = blockIdx.y * 128;

    float acc[8][8] = {};

    for (int k0 = 0; k0 < 128; k0 += 16) {
        // Load to regs first (overlap with previous tile's compute epoch)
        float4 av[2], bv[2];
        int rrow[2], rc4[2];
        #pragma unroll
        for (int q = 0; q < 2; q++) {
            int v = tid * 2 + q;          // 0..511 float4 ids
            rrow[q] = v >> 2;             // 0..127
            rc4[q]  = (v & 3) * 4;        // 0,4,8,12
            av[q] = *(const float4*)(Ap + (size_t)(m0 + rrow[q]) * 128 + k0 + rc4[q]);
            bv[q] = *(const float4*)(W  + (size_t)(n0 + rrow[q]) * 128 + k0 + rc4[q]);
        }
        __syncthreads();
        #pragma unroll
        for (int q = 0; q < 2; q++) {
            As[rc4[q] + 0][rrow[q]] = av[q].x; As[rc4[q] + 1][rrow[q]] = av[q].y;
            As[rc4[q] + 2][rrow[q]] = av[q].z; As[rc4[q] + 3][rrow[q]] = av[q].w;
            Bs[rc4[q] + 0][rrow[q]] = bv[q].x; Bs[rc4[q] + 1][rrow[q]] = bv[q].y;
            Bs[rc4[q] + 2][rrow[q]] = bv[q].z; Bs[rc4[q] + 3][rrow[q]] = bv[q].w;
        }
        __syncthreads();
        #pragma unroll
        for (int kk = 0; kk < 16; kk++) {
            float4 a0 = *(const float4*)&As[kk][ty * 4];
            float4 a1 = *(const float4*)&As[kk][64 + ty * 4];
            float4 b0 = *(const float4*)&Bs[kk][tx * 4];
            float4 b1 = *(const float4*)&Bs[kk][64 + tx * 4];
            float ar[8] = {a0.x, a0.y, a0.z, a0.w, a1.x, a1.y, a1.z, a1.w};
            float br[8] = {b0.x, b0.y, b0.z, b0.w, b1.x, b1.y, b1.z, b1.w};
            #pragma unroll
            for (int i = 0; i < 8; i++)
                #pragma unroll
                for (int j = 0; j < 8; j++)
                    acc[i][j] += ar[i] * br[j];
        }
        __syncthreads();
    }

    #pragma unroll
    for (int i = 0; i < 8; i++) {
        int m = m0 + ((i < 4) ? (ty * 4 + i) : (64 + ty * 4 + i - 4));
        int b = m / NTOK;
        int nn = m - b * NTOK;
        #pragma unroll
        for (int j = 0; j < 8; j++) {
            int n = n0 + ((j < 4) ? (tx * 4 + j) : (64 + tx * 4 + j - 4));
            float val = acc[i][j] + bias[n];
            if (epi == 0) {
                int which = n >> 7;        // 0=q,1=k,2=v
                int cc = n & 127;
                int h = cc >> 5;
                int d = cc & 31;
                size_t dst = ((size_t)(b * HEADS + h) * NTOK + nn) * HD + d;
                if (which == 0)      g_q[dst] = val * SCALE_C;
                else if (which == 1) g_k[dst] = val;
                else                 g_v[dst] = val;
            } else {
                Cout[(size_t)m * CDIM + n] = val;
            }
        }
    }
}

// One block per (window b, head h). Register-tiled attention.
// smem floats: qs 98*36, ks 98*36, vs 100*36, Ss 98*100, bias 507, rsum 98
#define QS_OFF 0
#define KS_OFF 3528
#define VS_OFF 7056
#define SS_OFF 10656
#define BS_OFF 20456
#define RS_OFF 20963
#define SM_FLOATS 21061

__global__ __launch_bounds__(256) void attn_kernel(const float* __restrict__ rel,
                                                   const float* __restrict__ mask,
                                                   int L)
{
    extern __shared__ float sm[];
    float* qs = sm + QS_OFF;
    float* ks = sm + KS_OFF;
    float* vs = sm + VS_OFF;
    float* Ss = sm + SS_OFF;
    float* bs = sm + BS_OFF;
    float* rsum = sm + RS_OFF;
    float* pacc = sm + QS_OFF;   // alias qs after S-phase (3136 <= 3528)

    int tid = threadIdx.x;
    int bh = blockIdx.x;
    int b = bh >> 2;
    int h = bh & 3;

    size_t base = (size_t)bh * (NTOK * HD);
    for (int idx = tid; idx < NTOK * HD; idx += 256) {
        int r = idx >> 5, c = idx & 31;
        qs[r * 36 + c] = g_q[base + idx];
        ks[r * 36 + c] = g_k[base + idx];
        vs[r * 36 + c] = g_v[base + idx];
    }
    if (tid < 72) vs[98 * 36 + tid] = 0.f;   // zero v rows 98..99 (padded j)
    for (int idx = tid; idx < 507; idx += 256) bs[idx] = rel[h * 507 + idx];
    __syncthreads();

    const float* mrow = mask + (size_t)(b % L) * (NTOK * NTOK);

    // ---- S = q @ k^T + bias + mask : 7x7 micro-tiles, float4 over k ----
    {
        int tx = tid & 15, ty = tid >> 4;
        if (ty < 14 && tx < 14) {
            int i0 = ty * 7, j0 = tx * 7;
            float acc[7][7] = {};
            #pragma unroll
            for (int k4 = 0; k4 < 8; k4++) {
                float4 a[7];
                #pragma unroll
                for (int r = 0; r < 7; r++)
                    a[r] = *(const float4*)&qs[(i0 + r) * 36 + k4 * 4];
                #pragma unroll
                for (int c = 0; c < 7; c++) {
                    float4 bq = *(const float4*)&ks[(j0 + c) * 36 + k4 * 4];
                    #pragma unroll
                    for (int r = 0; r < 7; r++)
                        acc[r][c] += a[r].x * bq.x + a[r].y * bq.y
                                   + a[r].z * bq.z + a[r].w * bq.w;
                }
            }
            #pragma unroll
            for (int r = 0; r < 7; r++) {
                int i = i0 + r;
                int ti = i / 49, ri = i - ti * 49, hi = ri / 7, wi = ri - hi * 7;
                #pragma unroll
                for (int c = 0; c < 7; c++) {
                    int j = j0 + c;
                    int tj = j / 49, rj = j - tj * 49, hj = rj / 7, wj = rj - hj * 7;
                    int ridx = (ti - tj + 1) * 169 + (hi - hj + 6) * 13 + (wi - wj + 6);
                    Ss[i * 100 + j] = acc[r][c] + bs[ridx] + mrow[i * NTOK + j];
                }
            }
        }
    }
    __syncthreads();

    // ---- softmax: warp per row, shuffle reductions ----
    {
        int lane = tid & 31, w = tid >> 5;
        for (int row = w; row < NTOK; row += 8) {
            float* Sr = Ss + row * 100;
            float v0 = Sr[lane];
            float v1 = Sr[lane + 32];
            float v2 = (lane + 64 < NTOK) ? Sr[lane + 64] : -1e30f;
            float v3 = (lane < 2) ? Sr[lane + 96] : -1e30f;
            float mx = fmaxf(fmaxf(v0, v1), fmaxf(v2, v3));
            #pragma unroll
            for (int s = 16; s > 0; s >>= 1)
                mx = fmaxf(mx, __shfl_xor_sync(0xFFFFFFFFu, mx, s));
            float e0 = __expf(v0 - mx), e1 = __expf(v1 - mx);
            float e2 = (lane + 64 < NTOK) ? __expf(v2 - mx) : 0.f;
            float e3 = (lane < 2) ? __expf(v3 - mx) : 0.f;
            float sum = e0 + e1 + e2 + e3;
            #pragma unroll
            for (int s = 16; s > 0; s >>= 1)
                sum += __shfl_xor_sync(0xFFFFFFFFu, sum, s);
            Sr[lane] = e0;
            Sr[lane + 32] = e1;
            if (lane + 64 < NTOK) Sr[lane + 64] = e2;
            if (lane < 2) Sr[lane + 96] = e3;
            if (lane < 2) Sr[98 + lane] = 0.f;    // zero padded cols
            if (lane == 0) rsum[row] = 1.f / sum;
        }
    }
    __syncthreads();

    // ---- O = P @ v : 7x4 micro-tiles, j split across 2 groups of 112 ----
    {
        float acc[7][4] = {};
        bool valid = tid < 224;
        int jh = tid / 112;
        int u = tid % 112;
        int txp = u & 7, typ = u >> 3;      // typ 0..13
        int i0 = typ * 7, d0 = txp * 4;
        if (valid) {
            int j4lo = jh ? 12 : 0;
            int j4hi = jh ? 25 : 12;        // 25*4 = 100 padded cols
            for (int j4 = j4lo; j4 < j4hi; j4++) {
                float4 bv[4];
                #pragma unroll
                for (int jj = 0; jj < 4; jj++)
                    bv[jj] = *(const float4*)&vs[(j4 * 4 + jj) * 36 + d0];
                #pragma unroll
                for (int r = 0; r < 7; r++) {
                    float4 p = *(const float4*)&Ss[(i0 + r) * 100 + j4 * 4];
                    acc[r][0] += p.x * bv[0].x + p.y * bv[1].x + p.z * bv[2].x + p.w * bv[3].x;
                    acc[r][1] += p.x * bv[0].y + p.y * bv[1].y + p.z * bv[2].y + p.w * bv[3].y;
                    acc[r][2] += p.x * bv[0].z + p.y * bv[1].z + p.z * bv[2].z + p.w * bv[3].z;
                    acc[r][3] += p.x * bv[0].w + p.y * bv[1].w + p.z * bv[2].w + p.w * bv[3].w;
                }
            }
            if (jh == 1) {
                #pragma unroll
                for (int r = 0; r < 7; r++)
                    #pragma unroll
                    for (int c = 0; c < 4; c++)
                        pacc[u * 28 + r * 4 + c] = acc[r][c];
            }
        }
        __syncthreads();
        if (valid && jh == 0) {
            #pragma unroll
            for (int r = 0; r < 7; r++) {
                float rs = rsum[i0 + r];
                float4 st;
                st.x = (acc[r][0] + pacc[u * 28 + r * 4 + 0]) * rs;
                st.y = (acc[r][1] + pacc[u * 28 + r * 4 + 1]) * rs;
                st.z = (acc[r][2] + pacc[u * 28 + r * 4 + 2]) * rs;
                st.w = (acc[r][3] + pacc[u * 28 + r * 4 + 3]) * rs;
                *(float4*)&g_o[((size_t)b * NTOK + i0 + r) * CDIM + h * HD + d0] = st;
            }
        }
    }
}

extern "C" void kernel_launch(void* const* d_in, const int* in_sizes, int n_in,
                              void* d_out, int out_size)
{
    const float* x      = (const float*)d_in[0];
    const float* mask   = (const float*)d_in[1];
    const float* qkv_w  = (const float*)d_in[2];
    const float* qkv_b  = (const float*)d_in[3];
    const float* rel    = (const float*)d_in[4];
    const float* proj_w = (const float*)d_in[5];
    const float* proj_b = (const float*)d_in[6];
    float* out = (float*)d_out;

    int B = in_sizes[0] / (NTOK * CDIM);        // 2048
    int L = in_sizes[1] / (NTOK * NTOK);        // 512
    int M = B * NTOK;                            // 200704

    const int smem_bytes = SM_FLOATS * (int)sizeof(float);  // 84244
    cudaFuncSetAttribute(attn_kernel, cudaFuncAttributeMaxDynamicSharedMemorySize, smem_bytes);

    dim3 g1(M / 128, 3);                         // qkv: (1568, 3)
    gemm128<<<g1, 256>>>(x, qkv_w, qkv_b, nullptr, 0);

    attn_kernel<<<B * HEADS, 256, smem_bytes>>>(rel, mask, L);

    dim3 g2(M / 128, 1);                         // proj
    gemm128<<<g2, 256>>>(nullptr, proj_w, proj_b, out, 1);
}

// round 9
// speedup vs baseline: 2.5543x; 1.4744x over previous
#include <cuda_runtime.h>
#include <cstdint>

#define HEADS 4
#define HD 32
#define NTOK 98
#define CDIM 128

static __device__ __constant__ float SCALE_C = 0.17677669529663687f; // 32^-0.5

// Scratch (device globals; no allocation allowed). Layout: [m][128] row-contig.
__device__ float g_q[(size_t)2048 * NTOK * CDIM];
__device__ float g_k[(size_t)2048 * NTOK * CDIM];
__device__ float g_v[(size_t)2048 * NTOK * CDIM];
__device__ float g_o[(size_t)2048 * NTOK * CDIM];

__device__ __forceinline__ uint32_t f2tf(float f) {
    uint32_t u;
    asm("cvt.rna.tf32.f32 %0, %1;" : "=r"(u) : "f"(f));
    return u;
}

__device__ __forceinline__ void mma_tf32(float c[4], uint32_t a0, uint32_t a1,
                                         uint32_t a2, uint32_t a3,
                                         uint32_t b0, uint32_t b1) {
    asm volatile(
        "mma.sync.aligned.m16n8k8.row.col.f32.tf32.tf32.f32 "
        "{%0,%1,%2,%3}, {%4,%5,%6,%7}, {%8,%9}, {%0,%1,%2,%3};"
        : "+f"(c[0]), "+f"(c[1]), "+f"(c[2]), "+f"(c[3])
        : "r"(a0), "r"(a1), "r"(a2), "r"(a3), "r"(b0), "r"(b1));
}

// ---------------- tf32 mma.sync GEMM ----------------
// C[M, ntiles*128] = A[M,128] @ W[ntiles*128,128]^T + bias
// epi==0: n-tile nt -> g_q/g_k/g_v (q scaled). epi==1: A := g_o, write Cout.
// smem: As 128x132 floats (tf32 bits), Bs 128x132.  Stride 132 (= 4 mod 32)
// makes every fragment pattern (8 rows x 4 cols) bank-conflict-free.
#define AS_F 16896   // 128*132
#define GEMM_SMEM (2 * AS_F * 4)

__global__ __launch_bounds__(256)
void gemm_mma(const float* __restrict__ A,
              const float* __restrict__ W,
              const float* __restrict__ bias,
              float* __restrict__ Cout,
              int ntiles, int epi)
{
    extern __shared__ float smf[];
    float* As = smf;
    float* Bs = smf + AS_F;

    int tid = threadIdx.x;
    int w = tid >> 5, l = tid & 31;
    int g = l >> 2, t4 = l & 3;
    int wm = w >> 1, wn = w & 1;       // 4 x 2 warp grid
    int m0 = blockIdx.x * 128;

    const float* Ap = (epi == 1) ? (const float*)g_o : A;

    // Load + tf32-convert A tile (128 rows x 128 cols)
    #pragma unroll
    for (int it = 0; it < 16; it++) {
        int idx = tid + it * 256;
        int r = idx >> 5, k4 = idx & 31;
        float4 v = *(const float4*)(Ap + (size_t)(m0 + r) * 128 + k4 * 4);
        uint32_t* d = (uint32_t*)&As[r * 132 + k4 * 4];
        d[0] = f2tf(v.x); d[1] = f2tf(v.y); d[2] = f2tf(v.z); d[3] = f2tf(v.w);
    }

    const uint32_t* a_base = (const uint32_t*)&As[(wm * 32 + g) * 132];
    const uint32_t* b_base = (const uint32_t*)&Bs[(wn * 64 + g) * 132];

    for (int nt = 0; nt < ntiles; nt++) {
        // Load + tf32-convert B tile (W rows nt*128 .. +127)
        #pragma unroll
        for (int it = 0; it < 16; it++) {
            int idx = tid + it * 256;
            int r = idx >> 5, k4 = idx & 31;
            float4 v = *(const float4*)(W + (size_t)(nt * 128 + r) * 128 + k4 * 4);
            uint32_t* d = (uint32_t*)&Bs[r * 132 + k4 * 4];
            d[0] = f2tf(v.x); d[1] = f2tf(v.y); d[2] = f2tf(v.z); d[3] = f2tf(v.w);
        }
        __syncthreads();

        float c[2][8][4];
        #pragma unroll
        for (int mi = 0; mi < 2; mi++)
            #pragma unroll
            for (int ni = 0; ni < 8; ni++)
                #pragma unroll
                for (int q = 0; q < 4; q++) c[mi][ni][q] = 0.f;

        #pragma unroll 2
        for (int k0 = 0; k0 < 128; k0 += 8) {
            uint32_t a[2][4];
            #pragma unroll
            for (int mi = 0; mi < 2; mi++) {
                const uint32_t* ab = a_base + mi * (16 * 132) + k0 + t4;
                a[mi][0] = ab[0];
                a[mi][1] = ab[8 * 132];
                a[mi][2] = ab[4];
                a[mi][3] = ab[8 * 132 + 4];
            }
            uint32_t b[8][2];
            #pragma unroll
            for (int ni = 0; ni < 8; ni++) {
                const uint32_t* bb = b_base + ni * (8 * 132) + k0 + t4;
                b[ni][0] = bb[0];
                b[ni][1] = bb[4];
            }
            #pragma unroll
            for (int mi = 0; mi < 2; mi++)
                #pragma unroll
                for (int ni = 0; ni < 8; ni++)
                    mma_tf32(c[mi][ni], a[mi][0], a[mi][1], a[mi][2], a[mi][3],
                             b[ni][0], b[ni][1]);
        }

        // Epilogue: fused bias (+scale), direct float2 stores
        {
            float* dst;
            const float* bp;
            float sc;
            if (epi == 0) {
                dst = (nt == 0) ? g_q : (nt == 1) ? g_k : g_v;
                bp = bias + nt * 128;
                sc = (nt == 0) ? SCALE_C : 1.0f;
            } else {
                dst = Cout;
                bp = bias;
                sc = 1.0f;
            }
            #pragma unroll
            for (int ni = 0; ni < 8; ni++) {
                int col = wn * 64 + ni * 8 + t4 * 2;
                float2 b2 = *(const float2*)(bp + col);
                #pragma unroll
                for (int mi = 0; mi < 2; mi++) {
                    int row0 = wm * 32 + mi * 16 + g;
                    float2 s0, s1;
                    s0.x = (c[mi][ni][0] + b2.x) * sc;
                    s0.y = (c[mi][ni][1] + b2.y) * sc;
                    s1.x = (c[mi][ni][2] + b2.x) * sc;
                    s1.y = (c[mi][ni][3] + b2.y) * sc;
                    *(float2*)&dst[(size_t)(m0 + row0) * 128 + col] = s0;
                    *(float2*)&dst[(size_t)(m0 + row0 + 8) * 128 + col] = s1;
                }
            }
        }
        __syncthreads();
    }
}

// ---------------- attention (R4-validated math; [m][128] qkv layout) ----------------
#define QS_OFF 0
#define KS_OFF 3528
#define VS_OFF 7056
#define SS_OFF 10656
#define BS_OFF 20456
#define RS_OFF 20963
#define SM_FLOATS 21061

__global__ __launch_bounds__(256) void attn_kernel(const float* __restrict__ rel,
                                                   const float* __restrict__ mask,
                                                   int L)
{
    extern __shared__ float sm[];
    float* qs = sm + QS_OFF;
    float* ks = sm + KS_OFF;
    float* vs = sm + VS_OFF;
    float* Ss = sm + SS_OFF;
    float* bs = sm + BS_OFF;
    float* rsum = sm + RS_OFF;
    float* pacc = sm + QS_OFF;   // alias qs after S-phase

    int tid = threadIdx.x;
    int bh = blockIdx.x;
    int b = bh >> 2;
    int h = bh & 3;

    size_t rowbase = (size_t)(b * NTOK) * CDIM + h * HD;
    for (int idx = tid; idx < NTOK * HD; idx += 256) {
        int r = idx >> 5, c = idx & 31;
        size_t src = rowbase + (size_t)r * CDIM + c;
        qs[r * 36 + c] = g_q[src];
        ks[r * 36 + c] = g_k[src];
        vs[r * 36 + c] = g_v[src];
    }
    if (tid < 72) vs[98 * 36 + tid] = 0.f;   // zero v rows 98..99 (padded j)
    for (int idx = tid; idx < 507; idx += 256) bs[idx] = rel[h * 507 + idx];
    __syncthreads();

    const float* mrow = mask + (size_t)(b % L) * (NTOK * NTOK);

    // ---- S = q @ k^T + bias + mask : 7x7 micro-tiles ----
    {
        int tx = tid & 15, ty = tid >> 4;
        if (ty < 14 && tx < 14) {
            int i0 = ty * 7, j0 = tx * 7;
            float acc[7][7] = {};
            #pragma unroll
            for (int k4 = 0; k4 < 8; k4++) {
                float4 a[7];
                #pragma unroll
                for (int r = 0; r < 7; r++)
                    a[r] = *(const float4*)&qs[(i0 + r) * 36 + k4 * 4];
                #pragma unroll
                for (int c = 0; c < 7; c++) {
                    float4 bq = *(const float4*)&ks[(j0 + c) * 36 + k4 * 4];
                    #pragma unroll
                    for (int r = 0; r < 7; r++)
                        acc[r][c] += a[r].x * bq.x + a[r].y * bq.y
                                   + a[r].z * bq.z + a[r].w * bq.w;
                }
            }
            #pragma unroll
            for (int r = 0; r < 7; r++) {
                int i = i0 + r;
                int ti = i / 49, ri = i - ti * 49, hi = ri / 7, wi = ri - hi * 7;
                #pragma unroll
                for (int c = 0; c < 7; c++) {
                    int j = j0 + c;
                    int tj = j / 49, rj = j - tj * 49, hj = rj / 7, wj = rj - hj * 7;
                    int ridx = (ti - tj + 1) * 169 + (hi - hj + 6) * 13 + (wi - wj + 6);
                    Ss[i * 100 + j] = acc[r][c] + bs[ridx] + mrow[i * NTOK + j];
                }
            }
        }
    }
    __syncthreads();

    // ---- softmax: warp per row ----
    {
        int lane = tid & 31, w = tid >> 5;
        for (int row = w; row < NTOK; row += 8) {
            float* Sr = Ss + row * 100;
            float v0 = Sr[lane];
            float v1 = Sr[lane + 32];
            float v2 = (lane + 64 < NTOK) ? Sr[lane + 64] : -1e30f;
            float v3 = (lane < 2) ? Sr[lane + 96] : -1e30f;
            float mx = fmaxf(fmaxf(v0, v1), fmaxf(v2, v3));
            #pragma unroll
            for (int s = 16; s > 0; s >>= 1)
                mx = fmaxf(mx, __shfl_xor_sync(0xFFFFFFFFu, mx, s));
            float e0 = __expf(v0 - mx), e1 = __expf(v1 - mx);
            float e2 = (lane + 64 < NTOK) ? __expf(v2 - mx) : 0.f;
            float e3 = (lane < 2) ? __expf(v3 - mx) : 0.f;
            float sum = e0 + e1 + e2 + e3;
            #pragma unroll
            for (int s = 16; s > 0; s >>= 1)
                sum += __shfl_xor_sync(0xFFFFFFFFu, sum, s);
            Sr[lane] = e0;
            Sr[lane + 32] = e1;
            if (lane + 64 < NTOK) Sr[lane + 64] = e2;
            if (lane < 2) Sr[lane + 96] = e3;
            if (lane < 2) Sr[98 + lane] = 0.f;
            if (lane == 0) rsum[row] = 1.f / sum;
        }
    }
    __syncthreads();

    // ---- O = P @ v : 7x4 micro-tiles, j split across 2 groups ----
    {
        float acc[7][4] = {};
        bool valid = tid < 224;
        int jh = tid / 112;
        int u = tid % 112;
        int txp = u & 7, typ = u >> 3;
        int i0 = typ * 7, d0 = txp * 4;
        if (valid) {
            int j4lo = jh ? 12 : 0;
            int j4hi = jh ? 25 : 12;
            for (int j4 = j4lo; j4 < j4hi; j4++) {
                float4 bv[4];
                #pragma unroll
                for (int jj = 0; jj < 4; jj++)
                    bv[jj] = *(const float4*)&vs[(j4 * 4 + jj) * 36 + d0];
                #pragma unroll
                for (int r = 0; r < 7; r++) {
                    float4 p = *(const float4*)&Ss[(i0 + r) * 100 + j4 * 4];
                    acc[r][0] += p.x * bv[0].x + p.y * bv[1].x + p.z * bv[2].x + p.w * bv[3].x;
                    acc[r][1] += p.x * bv[0].y + p.y * bv[1].y + p.z * bv[2].y + p.w * bv[3].y;
                    acc[r][2] += p.x * bv[0].z + p.y * bv[1].z + p.z * bv[2].z + p.w * bv[3].z;
                    acc[r][3] += p.x * bv[0].w + p.y * bv[1].w + p.z * bv[2].w + p.w * bv[3].w;
                }
            }
            if (jh == 1) {
                #pragma unroll
                for (int r = 0; r < 7; r++)
                    #pragma unroll
                    for (int c = 0; c < 4; c++)
                        pacc[u * 28 + r * 4 + c] = acc[r][c];
            }
        }
        __syncthreads();
        if (valid && jh == 0) {
            #pragma unroll
            for (int r = 0; r < 7; r++) {
                float rs = rsum[i0 + r];
                float4 st;
                st.x = (acc[r][0] + pacc[u * 28 + r * 4 + 0]) * rs;
                st.y = (acc[r][1] + pacc[u * 28 + r * 4 + 1]) * rs;
                st.z = (acc[r][2] + pacc[u * 28 + r * 4 + 2]) * rs;
                st.w = (acc[r][3] + pacc[u * 28 + r * 4 + 3]) * rs;
                *(float4*)&g_o[((size_t)b * NTOK + i0 + r) * CDIM + h * HD + d0] = st;
            }
        }
    }
}

extern "C" void kernel_launch(void* const* d_in, const int* in_sizes, int n_in,
                              void* d_out, int out_size)
{
    const float* x      = (const float*)d_in[0];
    const float* mask   = (const float*)d_in[1];
    const float* qkv_w  = (const float*)d_in[2];
    const float* qkv_b  = (const float*)d_in[3];
    const float* rel    = (const float*)d_in[4];
    const float* proj_w = (const float*)d_in[5];
    const float* proj_b = (const float*)d_in[6];
    float* out = (float*)d_out;

    int B = in_sizes[0] / (NTOK * CDIM);        // 2048
    int L = in_sizes[1] / (NTOK * NTOK);        // 512
    int M = B * NTOK;                            // 200704

    cudaFuncSetAttribute(gemm_mma, cudaFuncAttributeMaxDynamicSharedMemorySize, GEMM_SMEM);
    const int attn_smem = SM_FLOATS * (int)sizeof(float);
    cudaFuncSetAttribute(attn_kernel, cudaFuncAttributeMaxDynamicSharedMemorySize, attn_smem);

    gemm_mma<<<M / 128, 256, GEMM_SMEM>>>(x, qkv_w, qkv_b, nullptr, 3, 0);

    attn_kernel<<<B * HEADS, 256, attn_smem>>>(rel, mask, L);

    gemm_mma<<<M / 128, 256, GEMM_SMEM>>>(nullptr, proj_w, proj_b, out, 1, 1);
}

// round 11
// speedup vs baseline: 3.2441x; 1.2700x over previous
#include <cuda_runtime.h>
#include <cstdint>

#define HEADS 4
#define HD 32
#define NTOK 98
#define CDIM 128

static __device__ __constant__ float SCALE_C = 0.17677669529663687f; // 32^-0.5

// Scratch (device globals; no allocation allowed). Layout: [m][128] row-contig.
__device__ float g_q[(size_t)2048 * NTOK * CDIM];
__device__ float g_k[(size_t)2048 * NTOK * CDIM];
__device__ float g_v[(size_t)2048 * NTOK * CDIM];
__device__ float g_o[(size_t)2048 * NTOK * CDIM];

__device__ __forceinline__ uint32_t f2tf(float f) {
    uint32_t u;
    asm("cvt.rna.tf32.f32 %0, %1;" : "=r"(u) : "f"(f));
    return u;
}

__device__ __forceinline__ void mma_tf32(float c[4], uint32_t a0, uint32_t a1,
                                         uint32_t a2, uint32_t a3,
                                         uint32_t b0, uint32_t b1) {
    asm volatile(
        "mma.sync.aligned.m16n8k8.row.col.f32.tf32.tf32.f32 "
        "{%0,%1,%2,%3}, {%4,%5,%6,%7}, {%8,%9}, {%0,%1,%2,%3};"
        : "+f"(c[0]), "+f"(c[1]), "+f"(c[2]), "+f"(c[3])
        : "r"(a0), "r"(a1), "r"(a2), "r"(a3), "r"(b0), "r"(b1));
}

// ---------------- tf32 mma.sync GEMM (unchanged from R9) ----------------
#define AS_F 16896   // 128*132
#define GEMM_SMEM (2 * AS_F * 4)

__global__ __launch_bounds__(256)
void gemm_mma(const float* __restrict__ A,
              const float* __restrict__ W,
              const float* __restrict__ bias,
              float* __restrict__ Cout,
              int ntiles, int epi)
{
    extern __shared__ float smf[];
    float* As = smf;
    float* Bs = smf + AS_F;

    int tid = threadIdx.x;
    int w = tid >> 5, l = tid & 31;
    int g = l >> 2, t4 = l & 3;
    int wm = w >> 1, wn = w & 1;       // 4 x 2 warp grid
    int m0 = blockIdx.x * 128;

    const float* Ap = (epi == 1) ? (const float*)g_o : A;

    #pragma unroll
    for (int it = 0; it < 16; it++) {
        int idx = tid + it * 256;
        int r = idx >> 5, k4 = idx & 31;
        float4 v = *(const float4*)(Ap + (size_t)(m0 + r) * 128 + k4 * 4);
        uint32_t* d = (uint32_t*)&As[r * 132 + k4 * 4];
        d[0] = f2tf(v.x); d[1] = f2tf(v.y); d[2] = f2tf(v.z); d[3] = f2tf(v.w);
    }

    const uint32_t* a_base = (const uint32_t*)&As[(wm * 32 + g) * 132];
    const uint32_t* b_base = (const uint32_t*)&Bs[(wn * 64 + g) * 132];

    for (int nt = 0; nt < ntiles; nt++) {
        #pragma unroll
        for (int it = 0; it < 16; it++) {
            int idx = tid + it * 256;
            int r = idx >> 5, k4 = idx & 31;
            float4 v = *(const float4*)(W + (size_t)(nt * 128 + r) * 128 + k4 * 4);
            uint32_t* d = (uint32_t*)&Bs[r * 132 + k4 * 4];
            d[0] = f2tf(v.x); d[1] = f2tf(v.y); d[2] = f2tf(v.z); d[3] = f2tf(v.w);
        }
        __syncthreads();

        float c[2][8][4];
        #pragma unroll
        for (int mi = 0; mi < 2; mi++)
            #pragma unroll
            for (int ni = 0; ni < 8; ni++)
                #pragma unroll
                for (int q = 0; q < 4; q++) c[mi][ni][q] = 0.f;

        #pragma unroll 2
        for (int k0 = 0; k0 < 128; k0 += 8) {
            uint32_t a[2][4];
            #pragma unroll
            for (int mi = 0; mi < 2; mi++) {
                const uint32_t* ab = a_base + mi * (16 * 132) + k0 + t4;
                a[mi][0] = ab[0];
                a[mi][1] = ab[8 * 132];
                a[mi][2] = ab[4];
                a[mi][3] = ab[8 * 132 + 4];
            }
            uint32_t b[8][2];
            #pragma unroll
            for (int ni = 0; ni < 8; ni++) {
                const uint32_t* bb = b_base + ni * (8 * 132) + k0 + t4;
                b[ni][0] = bb[0];
                b[ni][1] = bb[4];
            }
            #pragma unroll
            for (int mi = 0; mi < 2; mi++)
                #pragma unroll
                for (int ni = 0; ni < 8; ni++)
                    mma_tf32(c[mi][ni], a[mi][0], a[mi][1], a[mi][2], a[mi][3],
                             b[ni][0], b[ni][1]);
        }

        {
            float* dst;
            const float* bp;
            float sc;
            if (epi == 0) {
                dst = (nt == 0) ? g_q : (nt == 1) ? g_k : g_v;
                bp = bias + nt * 128;
                sc = (nt == 0) ? SCALE_C : 1.0f;
            } else {
                dst = Cout;
                bp = bias;
                sc = 1.0f;
            }
            #pragma unroll
            for (int ni = 0; ni < 8; ni++) {
                int col = wn * 64 + ni * 8 + t4 * 2;
                float2 b2 = *(const float2*)(bp + col);
                #pragma unroll
                for (int mi = 0; mi < 2; mi++) {
                    int row0 = wm * 32 + mi * 16 + g;
                    float2 s0, s1;
                    s0.x = (c[mi][ni][0] + b2.x) * sc;
                    s0.y = (c[mi][ni][1] + b2.y) * sc;
                    s1.x = (c[mi][ni][2] + b2.x) * sc;
                    s1.y = (c[mi][ni][3] + b2.y) * sc;
                    *(float2*)&dst[(size_t)(m0 + row0) * 128 + col] = s0;
                    *(float2*)&dst[(size_t)(m0 + row0 + 8) * 128 + col] = s1;
                }
            }
        }
        __syncthreads();
    }
}

// ---------------- tensor-core attention ----------------
// One block per (window b, head h). 7 warps; warp w owns S rows 16w..16w+15
// of the padded 112x112 score matrix. m16n8k8 tf32 mma for S and PV.
// smem (floats): qs 112*36, ks 112*36, vt 32*116, Ss 112*116, bias 507
#define ATQ_OFF 0
#define ATK_OFF 4032
#define ATV_OFF 8064
#define ATS_OFF 11776
#define ATB_OFF 24768
#define AT_FLOATS 25275

__global__ __launch_bounds__(224)
void attn_mma(const float* __restrict__ rel,
              const float* __restrict__ mask,
              int L)
{
    extern __shared__ float sm[];
    uint32_t* qs = (uint32_t*)sm + ATQ_OFF;   // tf32 bits, stride 36
    uint32_t* ks = (uint32_t*)sm + ATK_OFF;   // stride 36
    uint32_t* vt = (uint32_t*)sm + ATV_OFF;   // v transposed [d][j], stride 116
    uint32_t* Ss = (uint32_t*)sm + ATS_OFF;   // P tf32, stride 116
    float*    bs = sm + ATB_OFF;              // 507

    int tid = threadIdx.x;
    int bh = blockIdx.x;
    int b = bh >> 2;
    int h = bh & 3;
    int w = tid >> 5, l = tid & 31;
    int g = l >> 2, t4 = l & 3;

    size_t rowbase = (size_t)(b * NTOK) * CDIM + h * HD;

    // Stage q, k (rows x 32, tf32) and v transposed
    #pragma unroll
    for (int it = 0; it < 14; it++) {
        int idx = tid + it * 224;
        int r = idx >> 5, c = idx & 31;
        float qv = g_q[rowbase + (size_t)r * CDIM + c];
        float kv = g_k[rowbase + (size_t)r * CDIM + c];
        float vv = g_v[rowbase + (size_t)r * CDIM + c];
        qs[r * 36 + c] = f2tf(qv);
        ks[r * 36 + c] = f2tf(kv);
        vt[c * 116 + r] = f2tf(vv);           // [d][j]
    }
    // zero v padded cols j=98..115
    for (int idx = tid; idx < 32 * 18; idx += 224) {
        int d = idx / 18, j = 98 + idx % 18;
        vt[d * 116 + j] = 0u;
    }
    for (int idx = tid; idx < 507; idx += 224) bs[idx] = rel[h * 507 + idx];
    __syncthreads();

    const float* mrow = mask + (size_t)(b % L) * (NTOK * NTOK);

    int i0 = w * 16;
    int iA = i0 + g, iB = iA + 8;

    // ---- S = q @ k^T via mma ----
    float c[14][4];
    #pragma unroll
    for (int ni = 0; ni < 14; ni++)
        #pragma unroll
        for (int q = 0; q < 4; q++) c[ni][q] = 0.f;

    {
        const uint32_t* ab = qs + (size_t)iA * 36 + t4;
        const uint32_t* bb = ks + (size_t)g * 36 + t4;
        #pragma unroll
        for (int k0 = 0; k0 < 32; k0 += 8) {
            uint32_t a0 = ab[k0], a1 = ab[8 * 36 + k0];
            uint32_t a2 = ab[k0 + 4], a3 = ab[8 * 36 + k0 + 4];
            #pragma unroll
            for (int ni = 0; ni < 14; ni++) {
                uint32_t b0 = bb[ni * 8 * 36 + k0];
                uint32_t b1 = bb[ni * 8 * 36 + k0 + 4];
                mma_tf32(c[ni], a0, a1, a2, a3, b0, b1);
            }
        }
    }

    // ---- bias + mask (in registers) ----
    int tiA = iA / 49, riA = iA - tiA * 49, hiA = riA / 7, wiA = riA - hiA * 7;
    int tiB = iB / 49, riB = iB - tiB * 49, hiB = riB / 7, wiB = riB - hiB * 7;
    #pragma unroll
    for (int ni = 0; ni < 14; ni++) {
        #pragma unroll
        for (int q = 0; q < 4; q++) {
            int j = ni * 8 + t4 * 2 + (q & 1);
            int i = (q < 2) ? iA : iB;
            if (j < NTOK && i < NTOK) {
                int tj = j / 49, rj = j - tj * 49, hj = rj / 7, wj = rj - hj * 7;
                int ti = (q < 2) ? tiA : tiB;
                int hi = (q < 2) ? hiA : hiB;
                int wi = (q < 2) ? wiA : wiB;
                int ridx = (ti - tj + 1) * 169 + (hi - hj + 6) * 13 + (wi - wj + 6);
                c[ni][q] += bs[ridx] + mrow[i * NTOK + j];
            } else {
                c[ni][q] = -1e30f;
            }
        }
    }

    // ---- softmax in registers (row = 4-lane t4 group) ----
    float m0 = -1e30f, m1 = -1e30f;
    #pragma unroll
    for (int ni = 0; ni < 14; ni++) {
        m0 = fmaxf(m0, fmaxf(c[ni][0], c[ni][1]));
        m1 = fmaxf(m1, fmaxf(c[ni][2], c[ni][3]));
    }
    m0 = fmaxf(m0, __shfl_xor_sync(0xFFFFFFFFu, m0, 1));
    m0 = fmaxf(m0, __shfl_xor_sync(0xFFFFFFFFu, m0, 2));
    m1 = fmaxf(m1, __shfl_xor_sync(0xFFFFFFFFu, m1, 1));
    m1 = fmaxf(m1, __shfl_xor_sync(0xFFFFFFFFu, m1, 2));
    float s0 = 0.f, s1 = 0.f;
    #pragma unroll
    for (int ni = 0; ni < 14; ni++) {
        c[ni][0] = __expf(c[ni][0] - m0);
        c[ni][1] = __expf(c[ni][1] - m0);
        c[ni][2] = __expf(c[ni][2] - m1);
        c[ni][3] = __expf(c[ni][3] - m1);
        s0 += c[ni][0] + c[ni][1];
        s1 += c[ni][2] + c[ni][3];
    }
    s0 += __shfl_xor_sync(0xFFFFFFFFu, s0, 1);
    s0 += __shfl_xor_sync(0xFFFFFFFFu, s0, 2);
    s1 += __shfl_xor_sync(0xFFFFFFFFu, s1, 1);
    s1 += __shfl_xor_sync(0xFFFFFFFFu, s1, 2);
    float inv0 = (iA < NTOK) ? (1.f / s0) : 0.f;   // padded rows -> 0
    float inv1 = (iB < NTOK) ? (1.f / s1) : 0.f;

    // store normalized P (tf32) to Ss
    #pragma unroll
    for (int ni = 0; ni < 14; ni++) {
        int j0 = ni * 8 + t4 * 2;
        uint2 pA, pB;
        pA.x = f2tf(c[ni][0] * inv0);
        pA.y = f2tf(c[ni][1] * inv0);
        pB.x = f2tf(c[ni][2] * inv1);
        pB.y = f2tf(c[ni][3] * inv1);
        *(uint2*)&Ss[(size_t)iA * 116 + j0] = pA;
        *(uint2*)&Ss[(size_t)iB * 116 + j0] = pB;
    }
    __syncthreads();

    // ---- O = P @ v via mma ----
    float o[4][4];
    #pragma unroll
    for (int ni = 0; ni < 4; ni++)
        #pragma unroll
        for (int q = 0; q < 4; q++) o[ni][q] = 0.f;

    {
        const uint32_t* ab = Ss + (size_t)iA * 116 + t4;
        const uint32_t* bb = vt + (size_t)g * 116 + t4;
        #pragma unroll
        for (int k0 = 0; k0 < 112; k0 += 8) {
            uint32_t a0 = ab[k0], a1 = ab[8 * 116 + k0];
            uint32_t a2 = ab[k0 + 4], a3 = ab[8 * 116 + k0 + 4];
            #pragma unroll
            for (int ni = 0; ni < 4; ni++) {
                uint32_t b0 = bb[ni * 8 * 116 + k0];
                uint32_t b1 = bb[ni * 8 * 116 + k0 + 4];
                mma_tf32(o[ni], a0, a1, a2, a3, b0, b1);
            }
        }
    }

    // write O (rows < 98 only)
    #pragma unroll
    for (int ni = 0; ni < 4; ni++) {
        int d0 = ni * 8 + t4 * 2;
        if (iA < NTOK) {
            float2 s; s.x = o[ni][0]; s.y = o[ni][1];
            *(float2*)&g_o[rowbase + (size_t)iA * CDIM + d0] = s;
        }
        if (iB < NTOK) {
            float2 s; s.x = o[ni][2]; s.y = o[ni][3];
            *(float2*)&g_o[rowbase + (size_t)iB * CDIM + d0] = s;
        }
    }
}

extern "C" void kernel_launch(void* const* d_in, const int* in_sizes, int n_in,
                              void* d_out, int out_size)
{
    const float* x      = (const float*)d_in[0];
    const float* mask   = (const float*)d_in[1];
    const float* qkv_w  = (const float*)d_in[2];
    const float* qkv_b  = (const float*)d_in[3];
    const float* rel    = (const float*)d_in[4];
    const float* proj_w = (const float*)d_in[5];
    const float* proj_b = (const float*)d_in[6];
    float* out = (float*)d_out;

    int B = in_sizes[0] / (NTOK * CDIM);        // 2048
    int L = in_sizes[1] / (NTOK * NTOK);        // 512
    int M = B * NTOK;                            // 200704

    cudaFuncSetAttribute(gemm_mma, cudaFuncAttributeMaxDynamicSharedMemorySize, GEMM_SMEM);
    const int attn_smem = AT_FLOATS * (int)sizeof(float);   // 101100
    cudaFuncSetAttribute(attn_mma, cudaFuncAttributeMaxDynamicSharedMemorySize, attn_smem);

    gemm_mma<<<M / 128, 256, GEMM_SMEM>>>(x, qkv_w, qkv_b, nullptr, 3, 0);

    attn_mma<<<B * HEADS, 224, attn_smem>>>(rel, mask, L);

    gemm_mma<<<M / 128, 256, GEMM_SMEM>>>(nullptr, proj_w, proj_b, out, 1, 1);
}

// round 13
// speedup vs baseline: 4.5355x; 1.3981x over previous
#include <cuda_runtime.h>
#include <cstdint>

#define HEADS 4
#define HD 32
#define NTOK 98
#define CDIM 128

static __device__ __constant__ float SCALE_C = 0.17677669529663687f; // 32^-0.5

// Scratch (device globals; no allocation allowed). Layout: [m][128] row-contig.
__device__ float g_q[(size_t)2048 * NTOK * CDIM];
__device__ float g_k[(size_t)2048 * NTOK * CDIM];
__device__ float g_v[(size_t)2048 * NTOK * CDIM];
__device__ float g_o[(size_t)2048 * NTOK * CDIM];

__device__ __forceinline__ uint32_t f2tf(float f) {
    uint32_t u;
    asm("cvt.rna.tf32.f32 %0, %1;" : "=r"(u) : "f"(f));
    return u;
}

__device__ __forceinline__ void mma_tf32(float c[4], uint32_t a0, uint32_t a1,
                                         uint32_t a2, uint32_t a3,
                                         uint32_t b0, uint32_t b1) {
    asm volatile(
        "mma.sync.aligned.m16n8k8.row.col.f32.tf32.tf32.f32 "
        "{%0,%1,%2,%3}, {%4,%5,%6,%7}, {%8,%9}, {%0,%1,%2,%3};"
        : "+f"(c[0]), "+f"(c[1]), "+f"(c[2]), "+f"(c[3])
        : "r"(a0), "r"(a1), "r"(a2), "r"(a3), "r"(b0), "r"(b1));
}

// ---------------- tf32 mma.sync GEMM, K-split B for 2 CTAs/SM ----------------
// As 128x132 (full K), Bs 128x68 (half K, double-pass). smem = 100 KB.
#define AS_F 16896   // 128*132
#define BS_F 8704    // 128*68
#define GEMM_SMEM ((AS_F + BS_F) * 4)

__global__ __launch_bounds__(256, 2)
void gemm_mma(const float* __restrict__ A,
              const float* __restrict__ W,
              const float* __restrict__ bias,
              float* __restrict__ Cout,
              int ntiles, int epi)
{
    extern __shared__ float smf[];
    float* As = smf;
    float* Bs = smf + AS_F;

    int tid = threadIdx.x;
    int w = tid >> 5, l = tid & 31;
    int g = l >> 2, t4 = l & 3;
    int wm = w >> 1, wn = w & 1;       // 4 x 2 warp grid
    int m0 = blockIdx.x * 128;

    const float* Ap = (epi == 1) ? (const float*)g_o : A;

    // Load + tf32-convert A tile (128 x 128)
    #pragma unroll
    for (int it = 0; it < 16; it++) {
        int idx = tid + it * 256;
        int r = idx >> 5, k4 = idx & 31;
        float4 v = *(const float4*)(Ap + (size_t)(m0 + r) * 128 + k4 * 4);
        uint32_t* d = (uint32_t*)&As[r * 132 + k4 * 4];
        d[0] = f2tf(v.x); d[1] = f2tf(v.y); d[2] = f2tf(v.z); d[3] = f2tf(v.w);
    }

    const uint32_t* a_base = (const uint32_t*)&As[(wm * 32 + g) * 132];
    const uint32_t* b_base = (const uint32_t*)&Bs[(wn * 64 + g) * 68];

    for (int nt = 0; nt < ntiles; nt++) {
        float c[2][8][4];
        #pragma unroll
        for (int mi = 0; mi < 2; mi++)
            #pragma unroll
            for (int ni = 0; ni < 8; ni++)
                #pragma unroll
                for (int q = 0; q < 4; q++) c[mi][ni][q] = 0.f;

        #pragma unroll
        for (int half = 0; half < 2; half++) {
            // Load B half: 128 rows x 64 cols
            #pragma unroll
            for (int it = 0; it < 8; it++) {
                int idx = tid + it * 256;          // 0..2047
                int r = idx >> 4, k4 = idx & 15;
                float4 v = *(const float4*)(W + (size_t)(nt * 128 + r) * 128
                                            + half * 64 + k4 * 4);
                uint32_t* d = (uint32_t*)&Bs[r * 68 + k4 * 4];
                d[0] = f2tf(v.x); d[1] = f2tf(v.y); d[2] = f2tf(v.z); d[3] = f2tf(v.w);
            }
            __syncthreads();

            #pragma unroll
            for (int k0 = 0; k0 < 64; k0 += 8) {
                uint32_t a[2][4];
                #pragma unroll
                for (int mi = 0; mi < 2; mi++) {
                    const uint32_t* ab = a_base + mi * (16 * 132) + half * 64 + k0 + t4;
                    a[mi][0] = ab[0];
                    a[mi][1] = ab[8 * 132];
                    a[mi][2] = ab[4];
                    a[mi][3] = ab[8 * 132 + 4];
                }
                uint32_t b[8][2];
                #pragma unroll
                for (int ni = 0; ni < 8; ni++) {
                    const uint32_t* bb = b_base + ni * (8 * 68) + k0 + t4;
                    b[ni][0] = bb[0];
                    b[ni][1] = bb[4];
                }
                #pragma unroll
                for (int mi = 0; mi < 2; mi++)
                    #pragma unroll
                    for (int ni = 0; ni < 8; ni++)
                        mma_tf32(c[mi][ni], a[mi][0], a[mi][1], a[mi][2], a[mi][3],
                                 b[ni][0], b[ni][1]);
            }
            __syncthreads();
        }

        // Epilogue: fused bias (+scale), float2 stores
        {
            float* dst;
            const float* bp;
            float sc;
            if (epi == 0) {
                dst = (nt == 0) ? g_q : (nt == 1) ? g_k : g_v;
                bp = bias + nt * 128;
                sc = (nt == 0) ? SCALE_C : 1.0f;
            } else {
                dst = Cout;
                bp = bias;
                sc = 1.0f;
            }
            #pragma unroll
            for (int ni = 0; ni < 8; ni++) {
                int col = wn * 64 + ni * 8 + t4 * 2;
                float2 b2 = *(const float2*)(bp + col);
                #pragma unroll
                for (int mi = 0; mi < 2; mi++) {
                    int row0 = wm * 32 + mi * 16 + g;
                    float2 s0, s1;
                    s0.x = (c[mi][ni][0] + b2.x) * sc;
                    s0.y = (c[mi][ni][1] + b2.y) * sc;
                    s1.x = (c[mi][ni][2] + b2.x) * sc;
                    s1.y = (c[mi][ni][3] + b2.y) * sc;
                    *(float2*)&dst[(size_t)(m0 + row0) * 128 + col] = s0;
                    *(float2*)&dst[(size_t)(m0 + row0 + 8) * 128 + col] = s1;
                }
            }
        }
    }
}

// ---------------- tensor-core attention, register-resident P ----------------
// One block per (window b, head h). 7 warps; warp w owns S rows 16w..16w+15.
// P never leaves registers: C-frag -> A-frag via intra-quad shuffles.
// smem (floats): qs 112*36, ks 112*36, vt 32*116, bias 507 = 49 KB
#define ATQ_OFF 0
#define ATK_OFF 4032
#define ATV_OFF 8064
#define ATB_OFF 11776
#define AT_FLOATS 12283

__global__ __launch_bounds__(224, 3)
void attn_mma(const float* __restrict__ rel,
              const float* __restrict__ mask,
              int L)
{
    extern __shared__ float sm[];
    uint32_t* qs = (uint32_t*)sm + ATQ_OFF;   // tf32 bits, stride 36
    uint32_t* ks = (uint32_t*)sm + ATK_OFF;   // stride 36
    uint32_t* vt = (uint32_t*)sm + ATV_OFF;   // v transposed [d][j], stride 116
    float*    bs = sm + ATB_OFF;              // 507

    int tid = threadIdx.x;
    int bh = blockIdx.x;
    int b = bh >> 2;
    int h = bh & 3;
    int w = tid >> 5, l = tid & 31;
    int g = l >> 2, t4 = l & 3;

    size_t rowbase = (size_t)(b * NTOK) * CDIM + h * HD;

    // Stage q, k (tf32) and v transposed
    #pragma unroll
    for (int it = 0; it < 14; it++) {
        int idx = tid + it * 224;
        int r = idx >> 5, c = idx & 31;
        float qv = g_q[rowbase + (size_t)r * CDIM + c];
        float kv = g_k[rowbase + (size_t)r * CDIM + c];
        float vv = g_v[rowbase + (size_t)r * CDIM + c];
        qs[r * 36 + c] = f2tf(qv);
        ks[r * 36 + c] = f2tf(kv);
        vt[c * 116 + r] = f2tf(vv);           // [d][j]
    }
    // zero v padded cols j=98..115 (avoid NaN/Inf garbage: 0*Inf)
    for (int idx = tid; idx < 32 * 18; idx += 224) {
        int d = idx / 18, j = 98 + idx % 18;
        vt[d * 116 + j] = 0u;
    }
    for (int idx = tid; idx < 507; idx += 224) bs[idx] = rel[h * 507 + idx];
    __syncthreads();

    const float* mrow = mask + (size_t)(b % L) * (NTOK * NTOK);

    int i0 = w * 16;
    int iA = i0 + g, iB = iA + 8;

    // ---- S = q @ k^T via mma ----
    float c[14][4];
    #pragma unroll
    for (int ni = 0; ni < 14; ni++)
        #pragma unroll
        for (int q = 0; q < 4; q++) c[ni][q] = 0.f;

    {
        const uint32_t* ab = qs + (size_t)iA * 36 + t4;
        const uint32_t* bb = ks + (size_t)g * 36 + t4;
        #pragma unroll
        for (int k0 = 0; k0 < 32; k0 += 8) {
            uint32_t a0 = ab[k0], a1 = ab[8 * 36 + k0];
            uint32_t a2 = ab[k0 + 4], a3 = ab[8 * 36 + k0 + 4];
            #pragma unroll
            for (int ni = 0; ni < 14; ni++) {
                uint32_t b0 = bb[ni * 8 * 36 + k0];
                uint32_t b1 = bb[ni * 8 * 36 + k0 + 4];
                mma_tf32(c[ni], a0, a1, a2, a3, b0, b1);
            }
        }
    }

    // ---- bias + mask (float2 mask loads) ----
    int tiA = iA / 49, riA = iA - tiA * 49, hiA = riA / 7, wiA = riA - hiA * 7;
    int tiB = iB / 49, riB = iB - tiB * 49, hiB = riB / 7, wiB = riB - hiB * 7;
    #pragma unroll
    for (int ni = 0; ni < 14; ni++) {
        int j0 = ni * 8 + t4 * 2;
        if (j0 < NTOK) {
            int tj0 = j0 / 49, rj0 = j0 - tj0 * 49, hj0 = rj0 / 7, wj0 = rj0 - hj0 * 7;
            int j1 = j0 + 1;
            int tj1 = j1 / 49, rj1 = j1 - tj1 * 49, hj1 = rj1 / 7, wj1 = rj1 - hj1 * 7;
            if (iA < NTOK) {
                float2 mv = *(const float2*)&mrow[iA * NTOK + j0];
                c[ni][0] += bs[(tiA - tj0 + 1) * 169 + (hiA - hj0 + 6) * 13 + (wiA - wj0 + 6)] + mv.x;
                c[ni][1] += bs[(tiA - tj1 + 1) * 169 + (hiA - hj1 + 6) * 13 + (wiA - wj1 + 6)] + mv.y;
            } else { c[ni][0] = -1e30f; c[ni][1] = -1e30f; }
            if (iB < NTOK) {
                float2 mv = *(const float2*)&mrow[iB * NTOK + j0];
                c[ni][2] += bs[(tiB - tj0 + 1) * 169 + (hiB - hj0 + 6) * 13 + (wiB - wj0 + 6)] + mv.x;
                c[ni][3] += bs[(tiB - tj1 + 1) * 169 + (hiB - hj1 + 6) * 13 + (wiB - wj1 + 6)] + mv.y;
            } else { c[ni][2] = -1e30f; c[ni][3] = -1e30f; }
        } else {
            c[ni][0] = -1e30f; c[ni][1] = -1e30f;
            c[ni][2] = -1e30f; c[ni][3] = -1e30f;
        }
    }

    // ---- softmax in registers (row = 4-lane quad) ----
    float m0 = -1e30f, m1 = -1e30f;
    #pragma unroll
    for (int ni = 0; ni < 14; ni++) {
        m0 = fmaxf(m0, fmaxf(c[ni][0], c[ni][1]));
        m1 = fmaxf(m1, fmaxf(c[ni][2], c[ni][3]));
    }
    m0 = fmaxf(m0, __shfl_xor_sync(0xFFFFFFFFu, m0, 1));
    m0 = fmaxf(m0, __shfl_xor_sync(0xFFFFFFFFu, m0, 2));
    m1 = fmaxf(m1, __shfl_xor_sync(0xFFFFFFFFu, m1, 1));
    m1 = fmaxf(m1, __shfl_xor_sync(0xFFFFFFFFu, m1, 2));
    float s0 = 0.f, s1 = 0.f;
    #pragma unroll
    for (int ni = 0; ni < 14; ni++) {
        c[ni][0] = __expf(c[ni][0] - m0);
        c[ni][1] = __expf(c[ni][1] - m0);
        c[ni][2] = __expf(c[ni][2] - m1);
        c[ni][3] = __expf(c[ni][3] - m1);
        s0 += c[ni][0] + c[ni][1];
        s1 += c[ni][2] + c[ni][3];
    }
    s0 += __shfl_xor_sync(0xFFFFFFFFu, s0, 1);
    s0 += __shfl_xor_sync(0xFFFFFFFFu, s0, 2);
    s1 += __shfl_xor_sync(0xFFFFFFFFu, s1, 1);
    s1 += __shfl_xor_sync(0xFFFFFFFFu, s1, 2);
    float inv0 = (iA < NTOK) ? (1.f / s0) : 0.f;   // padded rows -> P = 0
    float inv1 = (iB < NTOK) ? (1.f / s1) : 0.f;

    // normalize P in registers
    #pragma unroll
    for (int ni = 0; ni < 14; ni++) {
        c[ni][0] *= inv0; c[ni][1] *= inv0;
        c[ni][2] *= inv1; c[ni][3] *= inv1;
    }

    // ---- O = P @ v via mma; P C-frag -> A-frag via intra-quad shuffles ----
    float o[4][4];
    #pragma unroll
    for (int ni = 0; ni < 4; ni++)
        #pragma unroll
        for (int q = 0; q < 4; q++) o[ni][q] = 0.f;

    {
        int qb = l & ~3;
        int srcLo = qb + (t4 >> 1);        // owner of col t4   (pair t4>>1)
        int srcHi = qb + 2 + (t4 >> 1);    // owner of col t4+4
        bool odd = (t4 & 1) != 0;
        const uint32_t* bb = vt + (size_t)g * 116 + t4;
        #pragma unroll
        for (int kk = 0; kk < 14; kk++) {
            float s0a = __shfl_sync(0xFFFFFFFFu, c[kk][0], srcLo);
            float s0b = __shfl_sync(0xFFFFFFFFu, c[kk][1], srcLo);
            float s2a = __shfl_sync(0xFFFFFFFFu, c[kk][0], srcHi);
            float s2b = __shfl_sync(0xFFFFFFFFu, c[kk][1], srcHi);
            float s1a = __shfl_sync(0xFFFFFFFFu, c[kk][2], srcLo);
            float s1b = __shfl_sync(0xFFFFFFFFu, c[kk][3], srcLo);
            float s3a = __shfl_sync(0xFFFFFFFFu, c[kk][2], srcHi);
            float s3b = __shfl_sync(0xFFFFFFFFu, c[kk][3], srcHi);
            uint32_t a0 = f2tf(odd ? s0b : s0a);   // P[iA][8kk+t4]
            uint32_t a1 = f2tf(odd ? s1b : s1a);   // P[iB][8kk+t4]
            uint32_t a2 = f2tf(odd ? s2b : s2a);   // P[iA][8kk+t4+4]
            uint32_t a3 = f2tf(odd ? s3b : s3a);   // P[iB][8kk+t4+4]
            int k0 = kk * 8;
            #pragma unroll
            for (int ni = 0; ni < 4; ni++) {
                uint32_t b0 = bb[ni * 8 * 116 + k0];
                uint32_t b1 = bb[ni * 8 * 116 + k0 + 4];
                mma_tf32(o[ni], a0, a1, a2, a3, b0, b1);
            }
        }
    }

    // write O (rows < 98 only)
    #pragma unroll
    for (int ni = 0; ni < 4; ni++) {
        int d0 = ni * 8 + t4 * 2;
        if (iA < NTOK) {
            float2 s; s.x = o[ni][0]; s.y = o[ni][1];
            *(float2*)&g_o[rowbase + (size_t)iA * CDIM + d0] = s;
        }
        if (iB < NTOK) {
            float2 s; s.x = o[ni][2]; s.y = o[ni][3];
            *(float2*)&g_o[rowbase + (size_t)iB * CDIM + d0] = s;
        }
    }
}

extern "C" void kernel_launch(void* const* d_in, const int* in_sizes, int n_in,
                              void* d_out, int out_size)
{
    const float* x      = (const float*)d_in[0];
    const float* mask   = (const float*)d_in[1];
    const float* qkv_w  = (const float*)d_in[2];
    const float* qkv_b  = (const float*)d_in[3];
    const float* rel    = (const float*)d_in[4];
    const float* proj_w = (const float*)d_in[5];
    const float* proj_b = (const float*)d_in[6];
    float* out = (float*)d_out;

    int B = in_sizes[0] / (NTOK * CDIM);        // 2048
    int L = in_sizes[1] / (NTOK * NTOK);        // 512
    int M = B * NTOK;                            // 200704

    cudaFuncSetAttribute(gemm_mma, cudaFuncAttributeMaxDynamicSharedMemorySize, GEMM_SMEM);
    const int attn_smem = AT_FLOATS * (int)sizeof(float);   // 49132
    cudaFuncSetAttribute(attn_mma, cudaFuncAttributeMaxDynamicSharedMemorySize, attn_smem);

    gemm_mma<<<M / 128, 256, GEMM_SMEM>>>(x, qkv_w, qkv_b, nullptr, 3, 0);

    attn_mma<<<B * HEADS, 224, attn_smem>>>(rel, mask, L);

    gemm_mma<<<M / 128, 256, GEMM_SMEM>>>(nullptr, proj_w, proj_b, out, 1, 1);
}